// round 3
// baseline (speedup 1.0000x reference)
#include <cuda_runtime.h>

#define NCOEF 25
#define ROWS_PER_BLOCK 256
#define THREADS 256
#define BLK_FLOATS (ROWS_PER_BLOCK * NCOEF)   // 6400
#define BLK_FLOAT4 (BLK_FLOATS / 4)           // 1600

__global__ __launch_bounds__(THREADS)
void parcor_to_lpc_kernel(const float* __restrict__ in,
                          float* __restrict__ out,
                          int nrows, int ntiles)
{
    __shared__ float s[BLK_FLOATS];
    const int tid = threadIdx.x;

    for (int t = blockIdx.x; t < ntiles; t += gridDim.x) {
        const long long block_row0 = (long long)t * ROWS_PER_BLOCK;
        const bool full_block = (block_row0 + ROWS_PER_BLOCK) <= (long long)nrows;

        // ---- Phase 1: coalesced streaming float4 load into smem ----
        if (full_block) {
            const float4* __restrict__ gin =
                reinterpret_cast<const float4*>(in + block_row0 * NCOEF);
            float4* s4 = reinterpret_cast<float4*>(s);
            #pragma unroll
            for (int i = 0; i < 7; ++i) {
                int idx = tid + i * THREADS;
                if (idx < BLK_FLOAT4) s4[idx] = __ldcs(gin + idx);
            }
        } else {
            for (int idx = tid; idx < BLK_FLOATS; idx += THREADS) {
                long long r = block_row0 + idx / NCOEF;
                s[idx] = (r < (long long)nrows) ? __ldcs(in + r * NCOEF + (idx % NCOEF))
                                                : 0.0f;
            }
        }
        __syncthreads();

        // ---- Phase 2: per-thread in-register Levinson step-up ----
        {
            float a[NCOEF];
            #pragma unroll
            for (int j = 0; j < NCOEF; ++j) a[j] = s[tid * NCOEF + j];

            #pragma unroll
            for (int m = 2; m <= NCOEF - 1; ++m) {
                const float km = a[m];            // a[m] == k[m], never overwritten
                int i = 1, j = m - 1;
                #pragma unroll
                for (; i < j; ++i, --j) {
                    float ai = a[i], aj = a[j];
                    a[i] = fmaf(km, aj, ai);
                    a[j] = fmaf(km, ai, aj);
                }
                if (i == j) {
                    float ai = a[i];
                    a[i] = fmaf(km, ai, ai);
                }
            }
            // own-row writeback: no barrier needed between read and write
            #pragma unroll
            for (int j = 0; j < NCOEF; ++j) s[tid * NCOEF + j] = a[j];
        }
        __syncthreads();

        // ---- Phase 3: coalesced streaming float4 store ----
        if (full_block) {
            float4* __restrict__ gout =
                reinterpret_cast<float4*>(out + block_row0 * NCOEF);
            const float4* s4 = reinterpret_cast<const float4*>(s);
            #pragma unroll
            for (int i = 0; i < 7; ++i) {
                int idx = tid + i * THREADS;
                if (idx < BLK_FLOAT4) __stcs(gout + idx, s4[idx]);
            }
        } else {
            for (int idx = tid; idx < BLK_FLOATS; idx += THREADS) {
                long long r = block_row0 + idx / NCOEF;
                if (r < (long long)nrows) __stcs(out + r * NCOEF + (idx % NCOEF), s[idx]);
            }
        }
        __syncthreads();   // protect smem before next tile's load phase
    }
}

extern "C" void kernel_launch(void* const* d_in, const int* in_sizes, int n_in,
                              void* d_out, int out_size)
{
    const float* k = (const float*)d_in[0];
    float* out = (float*)d_out;
    int nrows = in_sizes[0] / NCOEF;                       // 2097152 on bench shape
    int ntiles = (nrows + ROWS_PER_BLOCK - 1) / ROWS_PER_BLOCK;

    int nblocks = 148 * 6;                                 // 6 reg-limited blocks/SM
    if (nblocks > ntiles) nblocks = ntiles;

    parcor_to_lpc_kernel<<<nblocks, THREADS>>>(k, out, nrows, ntiles);
}

// round 6
// speedup vs baseline: 1.0921x; 1.0921x over previous
#include <cuda_runtime.h>

#define NCOEF 25
#define ROWS_PER_BLOCK 256
#define THREADS 256
#define BLK_FLOATS (ROWS_PER_BLOCK * NCOEF)      // 6400
#define BLK_FLOAT4 (BLK_FLOATS / 4)              // 1600

__global__ __launch_bounds__(THREADS)
void parcor_to_lpc_kernel(const float* __restrict__ in,
                          float* __restrict__ out,
                          int nrows)
{
    __shared__ float s[BLK_FLOATS];

    const int tid = threadIdx.x;
    const long long block_row0 = (long long)blockIdx.x * ROWS_PER_BLOCK;

    const bool full_block = (block_row0 + ROWS_PER_BLOCK) <= (long long)nrows;

    if (full_block) {
        // ---- Phase 1: coalesced float4 load, L2-only (no L1 alloc) ----
        const float4* __restrict__ gin =
            reinterpret_cast<const float4*>(in + block_row0 * NCOEF);
        float4* s4 = reinterpret_cast<float4*>(s);
        #pragma unroll
        for (int i = 0; i < 7; ++i) {
            int idx = tid + i * THREADS;
            if (idx < BLK_FLOAT4) s4[idx] = __ldcg(gin + idx);
        }
    } else {
        for (int idx = tid; idx < BLK_FLOATS; idx += THREADS) {
            long long r = block_row0 + idx / NCOEF;
            s[idx] = (r < (long long)nrows) ? __ldcg(in + r * NCOEF + (idx % NCOEF))
                                            : 0.0f;
        }
    }
    __syncthreads();

    // ---- Phase 2: per-thread in-register Levinson step-up ----
    float a[NCOEF];
    #pragma unroll
    for (int j = 0; j < NCOEF; ++j) a[j] = s[tid * NCOEF + j];

    #pragma unroll
    for (int m = 2; m <= NCOEF - 1; ++m) {
        const float km = a[m];          // a[m] == k[m], never overwritten
        int i = 1, j = m - 1;
        #pragma unroll
        for (; i < j; ++i, --j) {
            float ai = a[i], aj = a[j];
            a[i] = fmaf(km, aj, ai);
            a[j] = fmaf(km, ai, aj);
        }
        if (i == j) {
            float ai = a[i];
            a[i] = fmaf(km, ai, ai);
        }
    }

    #pragma unroll
    for (int j = 0; j < NCOEF; ++j) s[tid * NCOEF + j] = a[j];
    __syncthreads();

    // ---- Phase 3: coalesced float4 store (default policy) ----
    if (full_block) {
        float4* __restrict__ gout =
            reinterpret_cast<float4*>(out + block_row0 * NCOEF);
        const float4* s4 = reinterpret_cast<const float4*>(s);
        #pragma unroll
        for (int i = 0; i < 7; ++i) {
            int idx = tid + i * THREADS;
            if (idx < BLK_FLOAT4) gout[idx] = s4[idx];
        }
    } else {
        for (int idx = tid; idx < BLK_FLOATS; idx += THREADS) {
            long long r = block_row0 + idx / NCOEF;
            if (r < (long long)nrows) out[r * NCOEF + (idx % NCOEF)] = s[idx];
        }
    }
}

extern "C" void kernel_launch(void* const* d_in, const int* in_sizes, int n_in,
                              void* d_out, int out_size)
{
    const float* k = (const float*)d_in[0];
    float* out = (float*)d_out;
    int nrows = in_sizes[0] / NCOEF;   // 2097152 for the bench shape
    int blocks = (nrows + ROWS_PER_BLOCK - 1) / ROWS_PER_BLOCK;
    parcor_to_lpc_kernel<<<blocks, THREADS>>>(k, out, nrows);
}

// round 7
// speedup vs baseline: 1.0969x; 1.0044x over previous
#include <cuda_runtime.h>

#define NCOEF 25
#define THREADS 256
#define WARPS (THREADS / 32)                  // 8
#define ROWS_PER_WARP 32
#define ROWS_PER_BLOCK (WARPS * ROWS_PER_WARP)  // 256
#define WARP_FLOATS (ROWS_PER_WARP * NCOEF)   // 800
#define WARP_F4 (WARP_FLOATS / 4)             // 200

__global__ __launch_bounds__(THREADS)
void parcor_warp_kernel(const float* __restrict__ in,
                        float* __restrict__ out,
                        int nrows)
{
    __shared__ float s[WARPS][WARP_FLOATS];

    const int warp = threadIdx.x >> 5;
    const int lane = threadIdx.x & 31;

    const long long warp_row0 =
        (long long)blockIdx.x * ROWS_PER_BLOCK + (long long)warp * ROWS_PER_WARP;
    const bool full = (warp_row0 + ROWS_PER_WARP) <= (long long)nrows;

    // ---- Phase 1 (warp-local): coalesced float4 load of 32 rows ----
    if (full) {
        const float4* __restrict__ g =
            reinterpret_cast<const float4*>(in + warp_row0 * NCOEF);
        float4* s4 = reinterpret_cast<float4*>(s[warp]);
        #pragma unroll
        for (int i = 0; i < 7; ++i) {
            int idx = lane + i * 32;
            if (idx < WARP_F4) s4[idx] = __ldcg(g + idx);
        }
    } else if (warp_row0 < (long long)nrows) {
        for (int f = lane; f < WARP_FLOATS; f += 32) {
            long long r = warp_row0 + f / NCOEF;
            s[warp][f] = (r < (long long)nrows) ? in[r * NCOEF + (f % NCOEF)] : 0.0f;
        }
    }
    __syncwarp();

    // ---- Phase 2: per-lane in-register Levinson step-up ----
    if (warp_row0 + lane < (long long)nrows) {
        float a[NCOEF];
        #pragma unroll
        for (int j = 0; j < NCOEF; ++j) a[j] = s[warp][lane * NCOEF + j];

        #pragma unroll
        for (int m = 2; m <= NCOEF - 1; ++m) {
            const float km = a[m];            // a[m] == k[m], never overwritten
            int i = 1, j = m - 1;
            #pragma unroll
            for (; i < j; ++i, --j) {
                float ai = a[i], aj = a[j];
                a[i] = fmaf(km, aj, ai);
                a[j] = fmaf(km, ai, aj);
            }
            if (i == j) {
                float ai = a[i];
                a[i] = fmaf(km, ai, ai);
            }
        }
        #pragma unroll
        for (int j = 0; j < NCOEF; ++j) s[warp][lane * NCOEF + j] = a[j];
    }
    __syncwarp();

    // ---- Phase 3 (warp-local): coalesced float4 store ----
    if (full) {
        float4* __restrict__ g =
            reinterpret_cast<float4*>(out + warp_row0 * NCOEF);
        const float4* s4 = reinterpret_cast<const float4*>(s[warp]);
        #pragma unroll
        for (int i = 0; i < 7; ++i) {
            int idx = lane + i * 32;
            if (idx < WARP_F4) g[idx] = s4[idx];
        }
    } else if (warp_row0 < (long long)nrows) {
        long long vfloat = ((long long)nrows - warp_row0) * NCOEF;
        if (vfloat > WARP_FLOATS) vfloat = WARP_FLOATS;
        for (int f = lane; f < (int)vfloat; f += 32)
            out[warp_row0 * NCOEF + f] = s[warp][f];
    }
}

extern "C" void kernel_launch(void* const* d_in, const int* in_sizes, int n_in,
                              void* d_out, int out_size)
{
    const float* k = (const float*)d_in[0];
    float* out = (float*)d_out;
    int nrows = in_sizes[0] / NCOEF;                   // 2097152 for the bench shape
    int blocks = (nrows + ROWS_PER_BLOCK - 1) / ROWS_PER_BLOCK;
    parcor_warp_kernel<<<blocks, THREADS>>>(k, out, nrows);
}